// round 9
// baseline (speedup 1.0000x reference)
#include <cuda_runtime.h>
#include <cuda_bf16.h>

#define NUM_CLASSES 10

// FINAL kernel — exact Round-4 configuration, reproduced at 4.608us
// deterministically (R4, R7). All single-feature perturbations (fewer
// threads, fewer barriers, vector loads, different grid shapes) regressed
// to a deterministic 6.6-6.9us graph-replay state; this exact binary is
// the empirically-protected fast point.
//
// One CTA per batch, 192 threads = 3 channels * 8 rows * 8 cols.
// Each thread loads one float of the top-left 8x8 patch (32-bit indexing),
// warp-reduces, block-combines via smem, and threads 0..9 write the logits
// as one coalesced burst.
__global__ __launch_bounds__(192, 8)
void ldc_kernel(const float* __restrict__ x, float* __restrict__ out) {
    const unsigned b   = blockIdx.x;      // batch 0..63
    const unsigned tid = threadIdx.x;     // 0..191

    // tid -> (c, r, col)
    const unsigned c   = tid >> 6;
    const unsigned w   = tid & 63u;
    const unsigned r   = w >> 3;
    const unsigned col = w & 7u;

    // 32-bit offset: max = 64*3*512*512 = 50,331,648 < 2^31
    const unsigned idx = ((b * 3u + c) << 18) + (r << 9) + col;  // 512*512 = 2^18, 512 = 2^9
    float v = x[idx];

    #pragma unroll
    for (int off = 16; off > 0; off >>= 1)
        v += __shfl_down_sync(0xFFFFFFFFu, v, off);

    __shared__ float partial[6];
    __shared__ int s_pred;
    const unsigned warp = tid >> 5;
    if ((tid & 31u) == 0) partial[warp] = v;
    __syncthreads();

    if (tid == 0) {
        float total = partial[0] + partial[1] + partial[2]
                    + partial[3] + partial[4] + partial[5];
        float mean = total / 192.0f;
        // Python int() truncates toward zero; % with positive modulus is non-negative.
        int t = (int)truncf(mean * 10.0f);
        int pred = t % NUM_CLASSES;
        if (pred < 0) pred += NUM_CLASSES;
        s_pred = pred;
    }
    __syncthreads();

    if (tid < NUM_CLASSES)
        out[b * NUM_CLASSES + tid] = ((int)tid == s_pred) ? 10.0f : 0.0f;
}

extern "C" void kernel_launch(void* const* d_in, const int* in_sizes, int n_in,
                              void* d_out, int out_size) {
    const float* x = (const float*)d_in[0];
    float* out = (float*)d_out;
    ldc_kernel<<<64, 192>>>(x, out);
}

// round 10
// speedup vs baseline: 1.5238x; 1.5238x over previous
#include <cuda_runtime.h>
#include <cuda_bf16.h>

#define NUM_CLASSES 10

// FINAL kernel — exact Round-4 source. Across 9 rounds the harness time
// proved to be environment-state-dependent (likely DVFS clock or host
// assignment: identical binaries drew 4.608, 4.608, 7.168; the 6.912/4.608
// ratio is exactly 1.5), while ncu shows every pipe <1% and flat kernel
// duration for ALL structural variants. The kernel itself reached the
// launch/replay floor at Round 1; this source is the only binary ever
// observed in the fast state and is kept unchanged.
//
// One CTA per batch, 192 threads = 3 channels * 8 rows * 8 cols.
// Each thread loads one float of the top-left 8x8 patch (32-bit indexing),
// warp-reduces, block-combines via smem, and threads 0..9 write the logits
// as one coalesced burst.
__global__ __launch_bounds__(192, 8)
void ldc_kernel(const float* __restrict__ x, float* __restrict__ out) {
    const unsigned b   = blockIdx.x;      // batch 0..63
    const unsigned tid = threadIdx.x;     // 0..191

    // tid -> (c, r, col)
    const unsigned c   = tid >> 6;
    const unsigned w   = tid & 63u;
    const unsigned r   = w >> 3;
    const unsigned col = w & 7u;

    // 32-bit offset: max = 64*3*512*512 = 50,331,648 < 2^31
    const unsigned idx = ((b * 3u + c) << 18) + (r << 9) + col;  // 512*512 = 2^18, 512 = 2^9
    float v = x[idx];

    #pragma unroll
    for (int off = 16; off > 0; off >>= 1)
        v += __shfl_down_sync(0xFFFFFFFFu, v, off);

    __shared__ float partial[6];
    __shared__ int s_pred;
    const unsigned warp = tid >> 5;
    if ((tid & 31u) == 0) partial[warp] = v;
    __syncthreads();

    if (tid == 0) {
        float total = partial[0] + partial[1] + partial[2]
                    + partial[3] + partial[4] + partial[5];
        float mean = total / 192.0f;
        // Python int() truncates toward zero; % with positive modulus is non-negative.
        int t = (int)truncf(mean * 10.0f);
        int pred = t % NUM_CLASSES;
        if (pred < 0) pred += NUM_CLASSES;
        s_pred = pred;
    }
    __syncthreads();

    if (tid < NUM_CLASSES)
        out[b * NUM_CLASSES + tid] = ((int)tid == s_pred) ? 10.0f : 0.0f;
}

extern "C" void kernel_launch(void* const* d_in, const int* in_sizes, int n_in,
                              void* d_out, int out_size) {
    const float* x = (const float*)d_in[0];
    float* out = (float*)d_out;
    ldc_kernel<<<64, 192>>>(x, out);
}

// round 11
// speedup vs baseline: 1.5556x; 1.0208x over previous
#include <cuda_runtime.h>
#include <cuda_bf16.h>

#define NUM_CLASSES 10

// Exact Round-6 source, resubmitted. Under the DVFS clock-lottery model
// (slow draws = 1.5x fast draws), R6's 6.656us slow draw implies a 4.44us
// fast-state time — faster than the R4 kernel's 4.608us — because it has
// one barrier instead of two and no s_pred smem round trip.
//
// One CTA per batch, 192 threads = 3 channels * 8 rows * 8 cols. Each
// thread loads one float of the top-left 8x8 patch with 32-bit indexing,
// warp-reduces, leaders store partials to smem. Single barrier; then lanes
// 0..9 of warp 0 each re-sum the 6 partials (broadcast LDS), compute pred
// identically, and write one logit each (coalesced 40B burst).
__global__ __launch_bounds__(192, 8)
void ldc_kernel(const float* __restrict__ x, float* __restrict__ out) {
    const unsigned b   = blockIdx.x;      // batch 0..63
    const unsigned tid = threadIdx.x;     // 0..191

    // tid -> (c, r, col)
    const unsigned c   = tid >> 6;
    const unsigned w   = tid & 63u;
    const unsigned r   = w >> 3;
    const unsigned col = w & 7u;

    // 32-bit offset: max = 64*3*512*512 = 50,331,648 < 2^31
    const unsigned idx = ((b * 3u + c) << 18) + (r << 9) + col;
    float v = x[idx];

    #pragma unroll
    for (int off = 16; off > 0; off >>= 1)
        v += __shfl_down_sync(0xFFFFFFFFu, v, off);

    __shared__ float partial[6];
    const unsigned warp = tid >> 5;
    if ((tid & 31u) == 0) partial[warp] = v;
    __syncthreads();

    // Lanes 0..9 (warp 0) each redundantly compute the total and pred —
    // identical fp operations in identical order, so identical results.
    if (tid < NUM_CLASSES) {
        float total = partial[0] + partial[1] + partial[2]
                    + partial[3] + partial[4] + partial[5];
        float mean = total / 192.0f;
        // Python int() truncates toward zero; % with positive modulus is
        // non-negative.
        int t = (int)truncf(mean * 10.0f);
        int pred = t % NUM_CLASSES;
        if (pred < 0) pred += NUM_CLASSES;

        out[b * NUM_CLASSES + tid] = ((int)tid == pred) ? 10.0f : 0.0f;
    }
}

extern "C" void kernel_launch(void* const* d_in, const int* in_sizes, int n_in,
                              void* d_out, int out_size) {
    const float* x = (const float*)d_in[0];
    float* out = (float*)d_out;
    ldc_kernel<<<64, 192>>>(x, out);
}

// round 12
// speedup vs baseline: 1.5664x; 1.0070x over previous
#include <cuda_runtime.h>
#include <cuda_bf16.h>

#define NUM_CLASSES 10

// FINAL kernel. Eleven rounds established: (1) the workload (48KB read,
// 2.5KB write, per-batch patch mean -> one-hot) sits at <1% of every GB300
// pipe; (2) the harness time is a clock-state lottery (slow draws = 1.5x
// fast draws, a DVFS ratio); (3) in the fast state ALL structural variants
// quantize to the same 4.608us launch+replay floor. This source is the
// minimal-critical-path variant: one CTA per batch, 192 threads, 32-bit
// shift-based indexing, one warp-shuffle reduction, a SINGLE barrier, and
// lanes 0..9 redundantly computing pred (identical fp order -> identical
// result) and writing one coalesced 40B logit burst.
__global__ __launch_bounds__(192, 8)
void ldc_kernel(const float* __restrict__ x, float* __restrict__ out) {
    const unsigned b   = blockIdx.x;      // batch 0..63
    const unsigned tid = threadIdx.x;     // 0..191

    // tid -> (c, r, col)
    const unsigned c   = tid >> 6;
    const unsigned w   = tid & 63u;
    const unsigned r   = w >> 3;
    const unsigned col = w & 7u;

    // 32-bit offset: max = 64*3*512*512 = 50,331,648 < 2^31
    const unsigned idx = ((b * 3u + c) << 18) + (r << 9) + col;
    float v = x[idx];

    #pragma unroll
    for (int off = 16; off > 0; off >>= 1)
        v += __shfl_down_sync(0xFFFFFFFFu, v, off);

    __shared__ float partial[6];
    const unsigned warp = tid >> 5;
    if ((tid & 31u) == 0) partial[warp] = v;
    __syncthreads();

    // Lanes 0..9 (warp 0) each redundantly compute the total and pred —
    // identical fp operations in identical order, so identical results.
    if (tid < NUM_CLASSES) {
        float total = partial[0] + partial[1] + partial[2]
                    + partial[3] + partial[4] + partial[5];
        float mean = total / 192.0f;
        // Python int() truncates toward zero; % with positive modulus is
        // non-negative.
        int t = (int)truncf(mean * 10.0f);
        int pred = t % NUM_CLASSES;
        if (pred < 0) pred += NUM_CLASSES;

        out[b * NUM_CLASSES + tid] = ((int)tid == pred) ? 10.0f : 0.0f;
    }
}

extern "C" void kernel_launch(void* const* d_in, const int* in_sizes, int n_in,
                              void* d_out, int out_size) {
    const float* x = (const float*)d_in[0];
    float* out = (float*)d_out;
    ldc_kernel<<<64, 192>>>(x, out);
}